// round 4
// baseline (speedup 1.0000x reference)
#include <cuda_runtime.h>
#include <cstdint>

#define NN 8192
#define EE 262144
#define DD 256
#define UMAX (EE + NN)
#define SLOT 128
#define BN_EPS 1e-5f

// GEMM tiling
#define BM 64
#define BNT 64
#define BK 32
#define ASTRIDE 36

// ---------------- device scratch (no allocations allowed) ----------------
__device__ unsigned g_bitmap[NN * (NN / 32)];   // 8 MB adjacency bit matrix
__device__ int      g_deg[NN];
__device__ int      g_nz;                        // nonzero-odd-word flag (int64 detect)
__device__ int      g_colidx[NN * SLOT];        // fixed-slot CSR (4 MB)
__device__ float    g_dinv[NN];
__device__ float    g_Z[NN * DD];               // GEMM output
__device__ float    g_Abuf[NN * DD];            // aggregation output
__device__ float    g_sum[3][DD];
__device__ float    g_sumsq[3][DD];

// ---------------- preprocessing ----------------

// int64 edge_index (values < 8192) => every odd 32-bit word zero.
__global__ void detect_k(const unsigned* __restrict__ e) {
    int i = blockIdx.x * blockDim.x + threadIdx.x;
    if (i < 4096 && e[2 * i + 1] != 0u) atomicOr(&g_nz, 1);
}

// Dedup via bitmap; winners place directly into fixed-slot CSR.
__global__ void dedup_k(const void* __restrict__ eptr) {
    int i = blockIdx.x * blockDim.x + threadIdx.x;
    if (i >= UMAX) return;
    int is64 = (g_nz == 0);
    int r, c;
    if (i < EE) {
        if (is64) {
            const long long* e = (const long long*)eptr;
            r = (int)e[i];
            c = (int)e[EE + i];
        } else {
            const int* e = (const int*)eptr;
            r = e[i];
            c = e[EE + i];
        }
    } else {
        r = c = i - EE;   // self loop
    }
    unsigned bit = (unsigned)r * NN + (unsigned)c;
    unsigned mask = 1u << (bit & 31u);
    unsigned old = atomicOr(&g_bitmap[bit >> 5], mask);
    if (!(old & mask)) {
        int slot = atomicAdd(&g_deg[r], 1);
        if (slot < SLOT) g_colidx[r * SLOT + slot] = c;
    }
}

__global__ void dinv_k() {
    int i = blockIdx.x * blockDim.x + threadIdx.x;
    if (i < NN) g_dinv[i] = rsqrtf((float)g_deg[i]);   // deg >= 1 (self loops)
}

// ---------------- GEMM: Z = act(A) @ W^T + b  (tf32 mma, cp.async pipeline) ----
__device__ __forceinline__ void cpa16(void* dst, const void* src) {
    unsigned d = (unsigned)__cvta_generic_to_shared(dst);
    asm volatile("cp.async.ca.shared.global [%0], [%1], 16;\n" :: "r"(d), "l"(src));
}
__device__ __forceinline__ unsigned to_tf32(float v) {
    unsigned u;
    asm("cvt.rna.tf32.f32 %0, %1;" : "=r"(u) : "f"(v));
    return u;
}

// fuse_layer < 0  : A used as-is (layer 1, raw x)
// fuse_layer >= 0 : A' = relu(BN(A)) applied on the SMEM->reg path
// 64x64 tile, 8 warps as 2(m) x 4(n), warp tile 32x16, double-buffered cp.async
__global__ __launch_bounds__(256, 4) void gemm_k(
    const float* __restrict__ Ain, const float* __restrict__ W,
    const float* __restrict__ bias, float* __restrict__ Z, int fuse_layer,
    const float* __restrict__ gamma, const float* __restrict__ beta)
{
    extern __shared__ float sm[];
    float* As  = sm;                               // [2][BM][ASTRIDE]
    float* Bs  = sm + 2 * BM * ASTRIDE;            // [2][BNT][ASTRIDE]
    float* ssc = sm + 2 * BM * ASTRIDE + 2 * BNT * ASTRIDE;
    float* ssh = ssc + DD;
#define AS(s,r,c) As[((s) * BM  + (r)) * ASTRIDE + (c)]
#define BS(s,r,c) Bs[((s) * BNT + (r)) * ASTRIDE + (c)]

    int tid = threadIdx.x;
    if (fuse_layer >= 0) {
        float mu = g_sum[fuse_layer][tid] * (1.f / NN);
        float var = g_sumsq[fuse_layer][tid] * (1.f / NN) - mu * mu;
        float rs = rsqrtf(var + BN_EPS);
        float sc = gamma[tid] * rs;
        ssc[tid] = sc;
        ssh[tid] = beta[tid] - mu * sc;
    }

    int bm = blockIdx.x * BM, bn = blockIdx.y * BNT;
    int wid = tid >> 5, lane = tid & 31;
    int g = lane >> 2, t = lane & 3;
    int wm = wid & 1, wn = wid >> 1;   // 2 x 4 warps, 32x16 per warp

    const float* Abase = Ain + (size_t)bm * DD;
    const float* Wbase = W + (size_t)bn * DD;

    float acc[2][2][4];
    #pragma unroll
    for (int mt = 0; mt < 2; mt++)
        #pragma unroll
        for (int nt = 0; nt < 2; nt++)
            #pragma unroll
            for (int q = 0; q < 4; q++) acc[mt][nt][q] = 0.f;

    // ---- prologue: issue stage 0 (A: 64x32 = 512 f4, B: same; 2+2 per thread)
    {
        #pragma unroll
        for (int it = 0; it < 2; it++) {
            int f = tid + it * 256;
            int r = f >> 3, c = (f & 7) * 4;
            cpa16(&AS(0, r, c), Abase + r * DD + c);
            cpa16(&BS(0, r, c), Wbase + r * DD + c);
        }
        asm volatile("cp.async.commit_group;");
    }
    __syncthreads();   // also covers ssc/ssh init visibility

    #pragma unroll 2
    for (int kb = 0; kb < DD / BK; kb++) {
        int s = kb & 1;
        int kglob = kb * BK;
        if (kb < DD / BK - 1) {
            int kn = kglob + BK;
            #pragma unroll
            for (int it = 0; it < 2; it++) {
                int f = tid + it * 256;
                int r = f >> 3, c = (f & 7) * 4;
                cpa16(&AS(s ^ 1, r, c), Abase + r * DD + kn + c);
                cpa16(&BS(s ^ 1, r, c), Wbase + r * DD + kn + c);
            }
            asm volatile("cp.async.commit_group;");
            asm volatile("cp.async.wait_group 1;");
        } else {
            asm volatile("cp.async.wait_group 0;");
        }
        __syncthreads();

        #pragma unroll
        for (int ks = 0; ks < 4; ks++) {
            int k8 = ks * 8;
            float sc0 = 0.f, sh0 = 0.f, sc1 = 0.f, sh1 = 0.f;
            if (fuse_layer >= 0) {
                sc0 = ssc[kglob + k8 + t];     sh0 = ssh[kglob + k8 + t];
                sc1 = ssc[kglob + k8 + t + 4]; sh1 = ssh[kglob + k8 + t + 4];
            }
            unsigned af[2][4], bf[2][2];
            #pragma unroll
            for (int mt = 0; mt < 2; mt++) {
                int rb = wm * 32 + mt * 16;
                float x0 = AS(s, rb + g,     k8 + t);
                float x1 = AS(s, rb + g + 8, k8 + t);
                float x2 = AS(s, rb + g,     k8 + t + 4);
                float x3 = AS(s, rb + g + 8, k8 + t + 4);
                if (fuse_layer >= 0) {
                    x0 = fmaxf(fmaf(x0, sc0, sh0), 0.f);
                    x1 = fmaxf(fmaf(x1, sc0, sh0), 0.f);
                    x2 = fmaxf(fmaf(x2, sc1, sh1), 0.f);
                    x3 = fmaxf(fmaf(x3, sc1, sh1), 0.f);
                }
                af[mt][0] = to_tf32(x0);
                af[mt][1] = to_tf32(x1);
                af[mt][2] = to_tf32(x2);
                af[mt][3] = to_tf32(x3);
            }
            #pragma unroll
            for (int nt = 0; nt < 2; nt++) {
                int nb = wn * 16 + nt * 8;
                bf[nt][0] = to_tf32(BS(s, nb + g, k8 + t));
                bf[nt][1] = to_tf32(BS(s, nb + g, k8 + t + 4));
            }
            #pragma unroll
            for (int mt = 0; mt < 2; mt++)
                #pragma unroll
                for (int nt = 0; nt < 2; nt++) {
                    asm volatile(
                        "mma.sync.aligned.m16n8k8.row.col.f32.tf32.tf32.f32 "
                        "{%0,%1,%2,%3},{%4,%5,%6,%7},{%8,%9},{%0,%1,%2,%3};"
                        : "+f"(acc[mt][nt][0]), "+f"(acc[mt][nt][1]),
                          "+f"(acc[mt][nt][2]), "+f"(acc[mt][nt][3])
                        : "r"(af[mt][0]), "r"(af[mt][1]), "r"(af[mt][2]), "r"(af[mt][3]),
                          "r"(bf[nt][0]), "r"(bf[nt][1]));
                }
        }
        __syncthreads();
    }

    // epilogue: += bias
    #pragma unroll
    for (int mt = 0; mt < 2; mt++)
        #pragma unroll
        for (int nt = 0; nt < 2; nt++) {
            int r0 = bm + wm * 32 + mt * 16 + g;
            int col = bn + wn * 16 + nt * 8 + 2 * t;
            float b0 = bias[col], b1 = bias[col + 1];
            Z[r0 * DD + col]           = acc[mt][nt][0] + b0;
            Z[r0 * DD + col + 1]       = acc[mt][nt][1] + b1;
            Z[(r0 + 8) * DD + col]     = acc[mt][nt][2] + b0;
            Z[(r0 + 8) * DD + col + 1] = acc[mt][nt][3] + b1;
        }
#undef AS
#undef BS
}

// ---------------- sparse aggregation + fused BN column stats ----------------
__global__ __launch_bounds__(256) void agg_k(const float* __restrict__ Z,
                                             float* __restrict__ Out, int layer) {
    __shared__ float sv[8][DD];
    int tid = threadIdx.x;
    int w = tid >> 5;                    // warp in block
    int row = blockIdx.x * 8 + w;
    int lane = tid & 31;

    int deg = g_deg[row];
    const int* cols = &g_colidx[row * SLOT];
    float4 a0 = make_float4(0.f, 0.f, 0.f, 0.f);
    float4 a1 = make_float4(0.f, 0.f, 0.f, 0.f);

    int p = 0;
    for (; p + 2 <= deg; p += 2) {
        int c0 = cols[p], c1 = cols[p + 1];
        float d0 = g_dinv[c0], d1 = g_dinv[c1];
        const float4* z0 = reinterpret_cast<const float4*>(Z + (size_t)c0 * DD);
        const float4* z1 = reinterpret_cast<const float4*>(Z + (size_t)c1 * DD);
        float4 u0 = __ldg(z0 + lane);
        float4 u1 = __ldg(z0 + lane + 32);
        float4 v0 = __ldg(z1 + lane);
        float4 v1 = __ldg(z1 + lane + 32);
        a0.x = fmaf(d0, u0.x, a0.x); a0.y = fmaf(d0, u0.y, a0.y);
        a0.z = fmaf(d0, u0.z, a0.z); a0.w = fmaf(d0, u0.w, a0.w);
        a1.x = fmaf(d0, u1.x, a1.x); a1.y = fmaf(d0, u1.y, a1.y);
        a1.z = fmaf(d0, u1.z, a1.z); a1.w = fmaf(d0, u1.w, a1.w);
        a0.x = fmaf(d1, v0.x, a0.x); a0.y = fmaf(d1, v0.y, a0.y);
        a0.z = fmaf(d1, v0.z, a0.z); a0.w = fmaf(d1, v0.w, a0.w);
        a1.x = fmaf(d1, v1.x, a1.x); a1.y = fmaf(d1, v1.y, a1.y);
        a1.z = fmaf(d1, v1.z, a1.z); a1.w = fmaf(d1, v1.w, a1.w);
    }
    for (; p < deg; p++) {
        int c = cols[p];
        float dv = g_dinv[c];
        const float4* zr = reinterpret_cast<const float4*>(Z + (size_t)c * DD);
        float4 v0 = __ldg(zr + lane);
        float4 v1 = __ldg(zr + lane + 32);
        a0.x = fmaf(dv, v0.x, a0.x); a0.y = fmaf(dv, v0.y, a0.y);
        a0.z = fmaf(dv, v0.z, a0.z); a0.w = fmaf(dv, v0.w, a0.w);
        a1.x = fmaf(dv, v1.x, a1.x); a1.y = fmaf(dv, v1.y, a1.y);
        a1.z = fmaf(dv, v1.z, a1.z); a1.w = fmaf(dv, v1.w, a1.w);
    }
    float dr = g_dinv[row];
    a0.x *= dr; a0.y *= dr; a0.z *= dr; a0.w *= dr;
    a1.x *= dr; a1.y *= dr; a1.z *= dr; a1.w *= dr;

    float4* orow = reinterpret_cast<float4*>(Out + (size_t)row * DD);
    orow[lane] = a0;
    orow[lane + 32] = a1;

    // fused BN stats: per-block column reduction then atomics
    *reinterpret_cast<float4*>(&sv[w][lane * 4])       = a0;
    *reinterpret_cast<float4*>(&sv[w][128 + lane * 4]) = a1;
    __syncthreads();
    float s = 0.f, ss = 0.f;
    #pragma unroll
    for (int r = 0; r < 8; r++) {
        float v = sv[r][tid];
        s += v;
        ss = fmaf(v, v, ss);
    }
    atomicAdd(&g_sum[layer][tid], s);
    atomicAdd(&g_sumsq[layer][tid], ss);
}

// final BN apply (no relu); scale/shift recomputed per block
__global__ __launch_bounds__(256) void apply_k(const float* __restrict__ A,
                                               float* __restrict__ out,
                                               const float* __restrict__ gamma,
                                               const float* __restrict__ beta) {
    __shared__ float ssc[DD], ssh[DD];
    int tid = threadIdx.x;
    {
        float mu = g_sum[2][tid] * (1.f / NN);
        float var = g_sumsq[2][tid] * (1.f / NN) - mu * mu;
        float rs = rsqrtf(var + BN_EPS);
        float sc = gamma[tid] * rs;
        ssc[tid] = sc;
        ssh[tid] = beta[tid] - mu * sc;
    }
    __syncthreads();
    int i = blockIdx.x * 256 + tid;          // float4 index
    int col = (i * 4) & (DD - 1);
    float4 v = reinterpret_cast<const float4*>(A)[i];
    float4 o;
    o.x = fmaf(v.x, ssc[col],     ssh[col]);
    o.y = fmaf(v.y, ssc[col + 1], ssh[col + 1]);
    o.z = fmaf(v.z, ssc[col + 2], ssh[col + 2]);
    o.w = fmaf(v.w, ssc[col + 3], ssh[col + 3]);
    reinterpret_cast<float4*>(out)[i] = o;
}

// ---------------- launch ----------------
extern "C" void kernel_launch(void* const* d_in, const int* in_sizes, int n_in,
                              void* d_out, int out_size) {
    const float* x   = (const float*)d_in[0];
    const void*  ei  = d_in[1];
    const float* W1  = (const float*)d_in[2];
    const float* b1  = (const float*)d_in[3];
    const float* W2  = (const float*)d_in[4];
    const float* b2  = (const float*)d_in[5];
    const float* W3  = (const float*)d_in[6];
    const float* b3  = (const float*)d_in[7];
    const float* g1  = (const float*)d_in[8];
    const float* be1 = (const float*)d_in[9];
    const float* g2  = (const float*)d_in[10];
    const float* be2 = (const float*)d_in[11];
    const float* g3  = (const float*)d_in[12];
    const float* be3 = (const float*)d_in[13];
    float* out = (float*)d_out;

    void *pZ, *pA, *pBm, *pDeg, *pSum, *pSq, *pNz;
    cudaGetSymbolAddress(&pZ, g_Z);
    cudaGetSymbolAddress(&pA, g_Abuf);
    cudaGetSymbolAddress(&pBm, g_bitmap);
    cudaGetSymbolAddress(&pDeg, g_deg);
    cudaGetSymbolAddress(&pSum, g_sum);
    cudaGetSymbolAddress(&pSq, g_sumsq);
    cudaGetSymbolAddress(&pNz, g_nz);
    float* Z  = (float*)pZ;
    float* Ab = (float*)pA;

    const int GEMM_SMEM = (2 * BM * ASTRIDE + 2 * BNT * ASTRIDE + 2 * DD) * 4;
    cudaFuncSetAttribute(gemm_k, cudaFuncAttributeMaxDynamicSharedMemorySize, GEMM_SMEM);

    // side stream + capture-safe events (created once, outside capture on the
    // correctness call; identical launch pattern every call)
    static cudaStream_t s_pre = nullptr;
    static cudaEvent_t ev_fork = nullptr, ev_join = nullptr;
    if (s_pre == nullptr) {
        cudaStreamCreateWithFlags(&s_pre, cudaStreamNonBlocking);
        cudaEventCreateWithFlags(&ev_fork, cudaEventDisableTiming);
        cudaEventCreateWithFlags(&ev_join, cudaEventDisableTiming);
    }

    // main-stream zeroing needed by agg (BN accumulators)
    cudaMemsetAsync(pSum, 0, sizeof(float) * 3 * DD);
    cudaMemsetAsync(pSq, 0, sizeof(float) * 3 * DD);

    // ---- fork: preprocessing on side stream, concurrent with layer-1 GEMM
    cudaEventRecord(ev_fork, 0);
    cudaStreamWaitEvent(s_pre, ev_fork, 0);
    cudaMemsetAsync(pBm, 0, sizeof(unsigned) * NN * (NN / 32), s_pre);
    cudaMemsetAsync(pDeg, 0, sizeof(int) * NN, s_pre);
    cudaMemsetAsync(pNz, 0, sizeof(int), s_pre);
    detect_k<<<16, 256, 0, s_pre>>>((const unsigned*)ei);
    dedup_k<<<(UMAX + 255) / 256, 256, 0, s_pre>>>(ei);
    dinv_k<<<NN / 256, 256, 0, s_pre>>>();
    cudaEventRecord(ev_join, s_pre);

    dim3 ggrid(NN / BM, DD / BNT);

    // layer 1 GEMM (needs only x, W1) runs concurrent with preprocessing
    gemm_k<<<ggrid, 256, GEMM_SMEM>>>(x, W1, b1, Z, -1, nullptr, nullptr);
    cudaStreamWaitEvent(0, ev_join, 0);   // join: agg needs CSR + dinv

    agg_k<<<NN / 8, 256>>>(Z, Ab, 0);
    // layer 2 (BN+ReLU fused into A path)
    gemm_k<<<ggrid, 256, GEMM_SMEM>>>(Ab, W2, b2, Z, 0, g1, be1);
    agg_k<<<NN / 8, 256>>>(Z, Ab, 1);
    // layer 3
    gemm_k<<<ggrid, 256, GEMM_SMEM>>>(Ab, W3, b3, Z, 1, g2, be2);
    agg_k<<<NN / 8, 256>>>(Z, Ab, 2);

    apply_k<<<NN * DD / 4 / 256, 256>>>(Ab, out, g3, be3);
}

// round 6
// speedup vs baseline: 1.3040x; 1.3040x over previous
#include <cuda_runtime.h>
#include <cuda_fp16.h>
#include <cstdint>

#define NN 8192
#define EE 262144
#define DD 256
#define UMAX (EE + NN)
#define SLOT 128
#define BN_EPS 1e-5f

// GEMM tiling (128x64 proven best)
#define BM 128
#define BNT 64
#define BK 32
#define ASTRIDE 36

// ---------------- device scratch ----------------
__device__ unsigned g_bitmap[NN * (NN / 32)];
__device__ int      g_deg[NN];
__device__ int      g_nz;
__device__ int      g_colidx[NN * SLOT];
__device__ float    g_dinv[NN];
__device__ unsigned g_Xtf[NN * DD];            // x pre-converted to tf32 bits
__device__ unsigned g_Wtf[3][DD * DD];         // weights pre-converted to tf32 bits
__device__ __half   g_Zh[NN * DD];             // GEMM output (fp16)
__device__ float    g_Abuf[NN * DD];           // aggregation output (fp32)
__device__ float    g_sum[3][DD];
__device__ float    g_sumsq[3][DD];

__device__ __forceinline__ unsigned to_tf32(float v) {
    unsigned u;
    asm("cvt.rna.tf32.f32 %0, %1;" : "=r"(u) : "f"(v));
    return u;
}

// ---------------- preprocessing ----------------
__global__ void detect_k(const unsigned* __restrict__ e) {
    int i = blockIdx.x * blockDim.x + threadIdx.x;
    if (i < 4096 && e[2 * i + 1] != 0u) atomicOr(&g_nz, 1);
}

__global__ void dedup_k(const void* __restrict__ eptr) {
    int i = blockIdx.x * blockDim.x + threadIdx.x;
    if (i >= UMAX) return;
    int is64 = (g_nz == 0);
    int r, c;
    if (i < EE) {
        if (is64) {
            const long long* e = (const long long*)eptr;
            r = (int)e[i];
            c = (int)e[EE + i];
        } else {
            const int* e = (const int*)eptr;
            r = e[i];
            c = e[EE + i];
        }
    } else {
        r = c = i - EE;   // self loop
    }
    unsigned bit = (unsigned)r * NN + (unsigned)c;
    unsigned mask = 1u << (bit & 31u);
    unsigned old = atomicOr(&g_bitmap[bit >> 5], mask);
    if (!(old & mask)) {
        int slot = atomicAdd(&g_deg[r], 1);
        if (slot < SLOT) g_colidx[r * SLOT + slot] = c;
    }
}

__global__ void dinv_k() {
    int i = blockIdx.x * blockDim.x + threadIdx.x;
    if (i < NN) g_dinv[i] = rsqrtf((float)g_deg[i]);
}

// ---------------- fp32 -> tf32-bits elementwise ----------------
__global__ void f2tf_k(const float4* __restrict__ in, uint4* __restrict__ out, int n4) {
    int i = blockIdx.x * blockDim.x + threadIdx.x;
    if (i >= n4) return;
    float4 v = in[i];
    uint4 u;
    u.x = to_tf32(v.x); u.y = to_tf32(v.y);
    u.z = to_tf32(v.z); u.w = to_tf32(v.w);
    out[i] = u;
}

// ---------------- GEMM: Zh = act(A) @ W^T + b  (tf32 mma, cp.async pipeline) --
__device__ __forceinline__ void cpa16(void* dst, const void* src) {
    unsigned d = (unsigned)__cvta_generic_to_shared(dst);
    asm volatile("cp.async.ca.shared.global [%0], [%1], 16;\n" :: "r"(d), "l"(src));
}

// fuse_layer < 0  : A holds tf32 bits already (layer 1: g_Xtf)  -> no cvt, no BN
// fuse_layer >= 0 : A holds fp32; A' = relu(BN(A)), cvt on the SMEM->reg path
__global__ __launch_bounds__(256, 2) void gemm_k(
    const void* __restrict__ Ain, const unsigned* __restrict__ W,
    const float* __restrict__ bias, __half* __restrict__ Z, int fuse_layer,
    const float* __restrict__ gamma, const float* __restrict__ beta)
{
    extern __shared__ float sm[];
    float* As  = sm;                               // [2][BM][ASTRIDE]
    float* Bs  = sm + 2 * BM * ASTRIDE;            // [2][BNT][ASTRIDE]
    float* ssc = sm + 2 * BM * ASTRIDE + 2 * BNT * ASTRIDE;
    float* ssh = ssc + DD;
#define AS(s,r,c) As[((s) * BM  + (r)) * ASTRIDE + (c)]
#define BS(s,r,c) Bs[((s) * BNT + (r)) * ASTRIDE + (c)]

    int tid = threadIdx.x;
    if (fuse_layer >= 0) {
        float mu = g_sum[fuse_layer][tid] * (1.f / NN);
        float var = g_sumsq[fuse_layer][tid] * (1.f / NN) - mu * mu;
        float rs = rsqrtf(var + BN_EPS);
        float sc = gamma[tid] * rs;
        ssc[tid] = sc;
        ssh[tid] = beta[tid] - mu * sc;
    }

    int bm = blockIdx.x * BM, bn = blockIdx.y * BNT;
    int wid = tid >> 5, lane = tid & 31;
    int g = lane >> 2, t = lane & 3;
    int wm = wid & 3, wn = wid >> 2;   // 4 x 2 warps, 32x32 per warp

    const float* Abase = (const float*)Ain + (size_t)bm * DD;
    const unsigned* Wbase = W + (size_t)bn * DD;

    float acc[2][4][4];
    #pragma unroll
    for (int mt = 0; mt < 2; mt++)
        #pragma unroll
        for (int nt = 0; nt < 4; nt++)
            #pragma unroll
            for (int q = 0; q < 4; q++) acc[mt][nt][q] = 0.f;

    // prologue: stage 0 (A 128x32 = 1024 f4: 4/thread; B 64x32 = 512 f4: 2/thread)
    {
        #pragma unroll
        for (int it = 0; it < 4; it++) {
            int f = tid + it * 256;
            int r = f >> 3, c = (f & 7) * 4;
            cpa16(&AS(0, r, c), Abase + r * DD + c);
        }
        #pragma unroll
        for (int it = 0; it < 2; it++) {
            int f = tid + it * 256;
            int r = f >> 3, c = (f & 7) * 4;
            cpa16(&BS(0, r, c), Wbase + r * DD + c);
        }
        asm volatile("cp.async.commit_group;");
    }
    __syncthreads();

    #pragma unroll 2
    for (int kb = 0; kb < DD / BK; kb++) {
        int s = kb & 1;
        int kglob = kb * BK;
        if (kb < DD / BK - 1) {
            int kn = kglob + BK;
            #pragma unroll
            for (int it = 0; it < 4; it++) {
                int f = tid + it * 256;
                int r = f >> 3, c = (f & 7) * 4;
                cpa16(&AS(s ^ 1, r, c), Abase + r * DD + kn + c);
            }
            #pragma unroll
            for (int it = 0; it < 2; it++) {
                int f = tid + it * 256;
                int r = f >> 3, c = (f & 7) * 4;
                cpa16(&BS(s ^ 1, r, c), Wbase + r * DD + kn + c);
            }
            asm volatile("cp.async.commit_group;");
            asm volatile("cp.async.wait_group 1;");
        } else {
            asm volatile("cp.async.wait_group 0;");
        }
        __syncthreads();

        #pragma unroll
        for (int ks = 0; ks < 4; ks++) {
            int k8 = ks * 8;
            unsigned af[2][4], bf[4][2];
            if (fuse_layer >= 0) {
                float sc0 = ssc[kglob + k8 + t],     sh0 = ssh[kglob + k8 + t];
                float sc1 = ssc[kglob + k8 + t + 4], sh1 = ssh[kglob + k8 + t + 4];
                #pragma unroll
                for (int mt = 0; mt < 2; mt++) {
                    int rb = wm * 32 + mt * 16;
                    float x0 = AS(s, rb + g,     k8 + t);
                    float x1 = AS(s, rb + g + 8, k8 + t);
                    float x2 = AS(s, rb + g,     k8 + t + 4);
                    float x3 = AS(s, rb + g + 8, k8 + t + 4);
                    af[mt][0] = to_tf32(fmaxf(fmaf(x0, sc0, sh0), 0.f));
                    af[mt][1] = to_tf32(fmaxf(fmaf(x1, sc0, sh0), 0.f));
                    af[mt][2] = to_tf32(fmaxf(fmaf(x2, sc1, sh1), 0.f));
                    af[mt][3] = to_tf32(fmaxf(fmaf(x3, sc1, sh1), 0.f));
                }
            } else {
                #pragma unroll
                for (int mt = 0; mt < 2; mt++) {
                    int rb = wm * 32 + mt * 16;
                    af[mt][0] = __float_as_uint(AS(s, rb + g,     k8 + t));
                    af[mt][1] = __float_as_uint(AS(s, rb + g + 8, k8 + t));
                    af[mt][2] = __float_as_uint(AS(s, rb + g,     k8 + t + 4));
                    af[mt][3] = __float_as_uint(AS(s, rb + g + 8, k8 + t + 4));
                }
            }
            #pragma unroll
            for (int nt = 0; nt < 4; nt++) {
                int nb = wn * 32 + nt * 8;
                bf[nt][0] = __float_as_uint(BS(s, nb + g, k8 + t));
                bf[nt][1] = __float_as_uint(BS(s, nb + g, k8 + t + 4));
            }
            #pragma unroll
            for (int mt = 0; mt < 2; mt++)
                #pragma unroll
                for (int nt = 0; nt < 4; nt++) {
                    asm volatile(
                        "mma.sync.aligned.m16n8k8.row.col.f32.tf32.tf32.f32 "
                        "{%0,%1,%2,%3},{%4,%5,%6,%7},{%8,%9},{%0,%1,%2,%3};"
                        : "+f"(acc[mt][nt][0]), "+f"(acc[mt][nt][1]),
                          "+f"(acc[mt][nt][2]), "+f"(acc[mt][nt][3])
                        : "r"(af[mt][0]), "r"(af[mt][1]), "r"(af[mt][2]), "r"(af[mt][3]),
                          "r"(bf[nt][0]), "r"(bf[nt][1]));
                }
        }
        __syncthreads();
    }

    // epilogue: += bias, convert to fp16
    #pragma unroll
    for (int mt = 0; mt < 2; mt++)
        #pragma unroll
        for (int nt = 0; nt < 4; nt++) {
            int r0 = bm + wm * 32 + mt * 16 + g;
            int col = bn + wn * 32 + nt * 8 + 2 * t;
            float b0 = bias[col], b1 = bias[col + 1];
            __half2 p0 = __floats2half2_rn(acc[mt][nt][0] + b0, acc[mt][nt][1] + b1);
            __half2 p1 = __floats2half2_rn(acc[mt][nt][2] + b0, acc[mt][nt][3] + b1);
            *reinterpret_cast<__half2*>(Z + (size_t)r0 * DD + col)       = p0;
            *reinterpret_cast<__half2*>(Z + (size_t)(r0 + 8) * DD + col) = p1;
        }
#undef AS
#undef BS
}

// ---------------- sparse aggregation (fp16 Z) + fused BN stats ----------------
__global__ __launch_bounds__(256) void agg_k(const __half* __restrict__ Z,
                                             float* __restrict__ Out, int layer) {
    __shared__ float sv[8][DD];
    int tid = threadIdx.x;
    int w = tid >> 5;
    int row = blockIdx.x * 8 + w;
    int lane = tid & 31;

    int deg = g_deg[row];
    const int* cols = &g_colidx[row * SLOT];
    float a[8];
    #pragma unroll
    for (int j = 0; j < 8; j++) a[j] = 0.f;

    // lane covers 8 consecutive fp16 columns: [lane*8, lane*8+8) via one uint4
    int p = 0;
    for (; p + 4 <= deg; p += 4) {
        int cc[4] = {cols[p], cols[p+1], cols[p+2], cols[p+3]};
        #pragma unroll
        for (int q = 0; q < 4; q++) {
            float dv = g_dinv[cc[q]];
            uint4 u = __ldg((const uint4*)(Z + (size_t)cc[q] * DD) + lane);
            float2 f0 = __half22float2(*reinterpret_cast<__half2*>(&u.x));
            float2 f1 = __half22float2(*reinterpret_cast<__half2*>(&u.y));
            float2 f2 = __half22float2(*reinterpret_cast<__half2*>(&u.z));
            float2 f3 = __half22float2(*reinterpret_cast<__half2*>(&u.w));
            a[0] = fmaf(dv, f0.x, a[0]); a[1] = fmaf(dv, f0.y, a[1]);
            a[2] = fmaf(dv, f1.x, a[2]); a[3] = fmaf(dv, f1.y, a[3]);
            a[4] = fmaf(dv, f2.x, a[4]); a[5] = fmaf(dv, f2.y, a[5]);
            a[6] = fmaf(dv, f3.x, a[6]); a[7] = fmaf(dv, f3.y, a[7]);
        }
    }
    for (; p < deg; p++) {
        int c = cols[p];
        float dv = g_dinv[c];
        uint4 u = __ldg((const uint4*)(Z + (size_t)c * DD) + lane);
        float2 f0 = __half22float2(*reinterpret_cast<__half2*>(&u.x));
        float2 f1 = __half22float2(*reinterpret_cast<__half2*>(&u.y));
        float2 f2 = __half22float2(*reinterpret_cast<__half2*>(&u.z));
        float2 f3 = __half22float2(*reinterpret_cast<__half2*>(&u.w));
        a[0] = fmaf(dv, f0.x, a[0]); a[1] = fmaf(dv, f0.y, a[1]);
        a[2] = fmaf(dv, f1.x, a[2]); a[3] = fmaf(dv, f1.y, a[3]);
        a[4] = fmaf(dv, f2.x, a[4]); a[5] = fmaf(dv, f2.y, a[5]);
        a[6] = fmaf(dv, f3.x, a[6]); a[7] = fmaf(dv, f3.y, a[7]);
    }
    float dr = g_dinv[row];
    #pragma unroll
    for (int j = 0; j < 8; j++) a[j] *= dr;

    float4* orow = reinterpret_cast<float4*>(Out + (size_t)row * DD);
    orow[lane * 2]     = make_float4(a[0], a[1], a[2], a[3]);
    orow[lane * 2 + 1] = make_float4(a[4], a[5], a[6], a[7]);

    // fused BN stats
    #pragma unroll
    for (int j = 0; j < 8; j++) sv[w][lane * 8 + j] = a[j];
    __syncthreads();
    float s = 0.f, ss = 0.f;
    #pragma unroll
    for (int r = 0; r < 8; r++) {
        float v = sv[r][tid];
        s += v;
        ss = fmaf(v, v, ss);
    }
    atomicAdd(&g_sum[layer][tid], s);
    atomicAdd(&g_sumsq[layer][tid], ss);
}

// final BN apply
__global__ __launch_bounds__(256) void apply_k(const float* __restrict__ A,
                                               float* __restrict__ out,
                                               const float* __restrict__ gamma,
                                               const float* __restrict__ beta) {
    __shared__ float ssc[DD], ssh[DD];
    int tid = threadIdx.x;
    {
        float mu = g_sum[2][tid] * (1.f / NN);
        float var = g_sumsq[2][tid] * (1.f / NN) - mu * mu;
        float rs = rsqrtf(var + BN_EPS);
        float sc = gamma[tid] * rs;
        ssc[tid] = sc;
        ssh[tid] = beta[tid] - mu * sc;
    }
    __syncthreads();
    int i = blockIdx.x * 256 + tid;
    int col = (i * 4) & (DD - 1);
    float4 v = reinterpret_cast<const float4*>(A)[i];
    float4 o;
    o.x = fmaf(v.x, ssc[col],     ssh[col]);
    o.y = fmaf(v.y, ssc[col + 1], ssh[col + 1]);
    o.z = fmaf(v.z, ssc[col + 2], ssh[col + 2]);
    o.w = fmaf(v.w, ssc[col + 3], ssh[col + 3]);
    reinterpret_cast<float4*>(out)[i] = o;
}

// ---------------- launch ----------------
extern "C" void kernel_launch(void* const* d_in, const int* in_sizes, int n_in,
                              void* d_out, int out_size) {
    const float* x   = (const float*)d_in[0];
    const void*  ei  = d_in[1];
    const float* W1  = (const float*)d_in[2];
    const float* b1  = (const float*)d_in[3];
    const float* W2  = (const float*)d_in[4];
    const float* b2  = (const float*)d_in[5];
    const float* W3  = (const float*)d_in[6];
    const float* b3  = (const float*)d_in[7];
    const float* g1  = (const float*)d_in[8];
    const float* be1 = (const float*)d_in[9];
    const float* g2  = (const float*)d_in[10];
    const float* be2 = (const float*)d_in[11];
    const float* g3  = (const float*)d_in[12];
    const float* be3 = (const float*)d_in[13];
    float* out = (float*)d_out;

    void *pZ, *pA, *pBm, *pDeg, *pSum, *pSq, *pNz, *pXtf, *pWtf;
    cudaGetSymbolAddress(&pZ, g_Zh);
    cudaGetSymbolAddress(&pA, g_Abuf);
    cudaGetSymbolAddress(&pBm, g_bitmap);
    cudaGetSymbolAddress(&pDeg, g_deg);
    cudaGetSymbolAddress(&pSum, g_sum);
    cudaGetSymbolAddress(&pSq, g_sumsq);
    cudaGetSymbolAddress(&pNz, g_nz);
    cudaGetSymbolAddress(&pXtf, g_Xtf);
    cudaGetSymbolAddress(&pWtf, g_Wtf);
    __half* Zh = (__half*)pZ;
    float* Ab = (float*)pA;
    unsigned* Xtf = (unsigned*)pXtf;
    unsigned* Wtf = (unsigned*)pWtf;

    const int GEMM_SMEM = (2 * BM * ASTRIDE + 2 * BNT * ASTRIDE + 2 * DD) * 4;
    cudaFuncSetAttribute(gemm_k, cudaFuncAttributeMaxDynamicSharedMemorySize, GEMM_SMEM);

    static cudaStream_t s_pre = nullptr;
    static cudaEvent_t ev_fork = nullptr, ev_join = nullptr;
    if (s_pre == nullptr) {
        cudaStreamCreateWithFlags(&s_pre, cudaStreamNonBlocking);
        cudaEventCreateWithFlags(&ev_fork, cudaEventDisableTiming);
        cudaEventCreateWithFlags(&ev_join, cudaEventDisableTiming);
    }

    // main-stream zeroing for BN accumulators
    cudaMemsetAsync(pSum, 0, sizeof(float) * 3 * DD);
    cudaMemsetAsync(pSq, 0, sizeof(float) * 3 * DD);

    // ---- fork: preprocessing concurrent with conversions + layer-1 GEMM
    cudaEventRecord(ev_fork, 0);
    cudaStreamWaitEvent(s_pre, ev_fork, 0);
    cudaMemsetAsync(pBm, 0, sizeof(unsigned) * NN * (NN / 32), s_pre);
    cudaMemsetAsync(pDeg, 0, sizeof(int) * NN, s_pre);
    cudaMemsetAsync(pNz, 0, sizeof(int), s_pre);
    detect_k<<<16, 256, 0, s_pre>>>((const unsigned*)ei);
    dedup_k<<<(UMAX + 255) / 256, 256, 0, s_pre>>>(ei);
    dinv_k<<<NN / 256, 256, 0, s_pre>>>();
    cudaEventRecord(ev_join, s_pre);

    // main: tf32 conversions (prereqs of gemm1)
    f2tf_k<<<(NN * DD / 4 + 255) / 256, 256>>>(
        (const float4*)x, (uint4*)Xtf, NN * DD / 4);
    f2tf_k<<<(DD * DD / 4 + 255) / 256, 256>>>(
        (const float4*)W1, (uint4*)(Wtf + 0 * DD * DD), DD * DD / 4);
    f2tf_k<<<(DD * DD / 4 + 255) / 256, 256>>>(
        (const float4*)W2, (uint4*)(Wtf + 1 * DD * DD), DD * DD / 4);
    f2tf_k<<<(DD * DD / 4 + 255) / 256, 256>>>(
        (const float4*)W3, (uint4*)(Wtf + 2 * DD * DD), DD * DD / 4);

    dim3 ggrid(NN / BM, DD / BNT);

    // layer 1 (tf32 A, no BN) — concurrent with preprocessing fork
    gemm_k<<<ggrid, 256, GEMM_SMEM>>>(Xtf, Wtf + 0 * DD * DD, b1, Zh, -1, nullptr, nullptr);
    cudaStreamWaitEvent(0, ev_join, 0);   // agg needs CSR + dinv

    agg_k<<<NN / 8, 256>>>(Zh, Ab, 0);
    gemm_k<<<ggrid, 256, GEMM_SMEM>>>(Ab, Wtf + 1 * DD * DD, b2, Zh, 0, g1, be1);
    agg_k<<<NN / 8, 256>>>(Zh, Ab, 1);
    gemm_k<<<ggrid, 256, GEMM_SMEM>>>(Ab, Wtf + 2 * DD * DD, b3, Zh, 1, g2, be2);
    agg_k<<<NN / 8, 256>>>(Zh, Ab, 2);

    apply_k<<<NN * DD / 4 / 256, 256>>>(Ab, out, g3, be3);
}

// round 7
// speedup vs baseline: 1.4055x; 1.0779x over previous
#include <cuda_runtime.h>
#include <cuda_fp16.h>
#include <cstdint>

#define NN 8192
#define EE 262144
#define DD 256
#define UMAX (EE + NN)
#define SLOT 128
#define BN_EPS 1e-5f

// GEMM tiling
#define BM 128
#define BNT 64
#define BK 32
#define ASH 40   // smem stride in halves (80B: conflict-free for frag loads)

// ---------------- device scratch ----------------
__device__ unsigned g_bitmap[NN * (NN / 32)];
__device__ int      g_deg[NN];
__device__ int      g_nz;
__device__ int      g_colidx[NN * SLOT];
__device__ float    g_dinv[NN];
__device__ __half   g_Xh[NN * DD];             // x in fp16
__device__ __half   g_Wh[3][DD * DD];          // weights in fp16
__device__ __half   g_Ah[NN * DD];             // BN(relu(agg)) in fp16 (GEMM A input)
__device__ __half   g_Zh[NN * DD];             // GEMM output (fp16)
__device__ float    g_Abuf[NN * DD];           // aggregation output (fp32)
__device__ float    g_sum[3][DD];
__device__ float    g_sumsq[3][DD];

// ---------------- preprocessing ----------------
__global__ void detect_k(const unsigned* __restrict__ e) {
    int i = blockIdx.x * blockDim.x + threadIdx.x;
    if (i < 4096 && e[2 * i + 1] != 0u) atomicOr(&g_nz, 1);
}

__global__ void dedup_k(const void* __restrict__ eptr) {
    int i = blockIdx.x * blockDim.x + threadIdx.x;
    if (i >= UMAX) return;
    int is64 = (g_nz == 0);
    int r, c;
    if (i < EE) {
        if (is64) {
            const long long* e = (const long long*)eptr;
            r = (int)e[i];
            c = (int)e[EE + i];
        } else {
            const int* e = (const int*)eptr;
            r = e[i];
            c = e[EE + i];
        }
    } else {
        r = c = i - EE;   // self loop
    }
    unsigned bit = (unsigned)r * NN + (unsigned)c;
    unsigned mask = 1u << (bit & 31u);
    unsigned old = atomicOr(&g_bitmap[bit >> 5], mask);
    if (!(old & mask)) {
        int slot = atomicAdd(&g_deg[r], 1);
        if (slot < SLOT) g_colidx[r * SLOT + slot] = c;
    }
}

__global__ void dinv_k() {
    int i = blockIdx.x * blockDim.x + threadIdx.x;
    if (i < NN) g_dinv[i] = rsqrtf((float)g_deg[i]);
}

// ---------------- fp32 -> fp16 elementwise ----------------
__global__ void f2h_k(const float4* __restrict__ in, uint2* __restrict__ out, int n4) {
    int i = blockIdx.x * blockDim.x + threadIdx.x;
    if (i >= n4) return;
    float4 v = in[i];
    __half2 lo = __floats2half2_rn(v.x, v.y);
    __half2 hi = __floats2half2_rn(v.z, v.w);
    uint2 u;
    u.x = *reinterpret_cast<unsigned*>(&lo);
    u.y = *reinterpret_cast<unsigned*>(&hi);
    out[i] = u;
}

// ---------------- BN + ReLU + cvt: Ah = fp16(relu(BN(Ab))) ----------------
__global__ __launch_bounds__(256) void bnrelu_k(const float* __restrict__ A,
                                                __half* __restrict__ Out, int layer,
                                                const float* __restrict__ gamma,
                                                const float* __restrict__ beta) {
    __shared__ float ssc[DD], ssh[DD];
    int tid = threadIdx.x;
    {
        float mu = g_sum[layer][tid] * (1.f / NN);
        float var = g_sumsq[layer][tid] * (1.f / NN) - mu * mu;
        float rs = rsqrtf(var + BN_EPS);
        float sc = gamma[tid] * rs;
        ssc[tid] = sc;
        ssh[tid] = beta[tid] - mu * sc;
    }
    __syncthreads();
    int i = blockIdx.x * 256 + tid;             // float4 index
    int col = (i * 4) & (DD - 1);
    float4 v = reinterpret_cast<const float4*>(A)[i];
    float a = fmaxf(fmaf(v.x, ssc[col],     ssh[col]),     0.f);
    float b = fmaxf(fmaf(v.y, ssc[col + 1], ssh[col + 1]), 0.f);
    float c = fmaxf(fmaf(v.z, ssc[col + 2], ssh[col + 2]), 0.f);
    float d = fmaxf(fmaf(v.w, ssc[col + 3], ssh[col + 3]), 0.f);
    __half2 lo = __floats2half2_rn(a, b);
    __half2 hi = __floats2half2_rn(c, d);
    uint2 u;
    u.x = *reinterpret_cast<unsigned*>(&lo);
    u.y = *reinterpret_cast<unsigned*>(&hi);
    reinterpret_cast<uint2*>(Out)[i] = u;
}

// ---------------- GEMM: Zh = A @ W^T + b  (fp16 HMMA m16n8k16, cp.async) ------
__device__ __forceinline__ void cpa16(void* dst, const void* src) {
    unsigned d = (unsigned)__cvta_generic_to_shared(dst);
    asm volatile("cp.async.ca.shared.global [%0], [%1], 16;\n" :: "r"(d), "l"(src));
}

__global__ __launch_bounds__(256, 2) void gemm_k(
    const __half* __restrict__ Ain, const __half* __restrict__ W,
    const float* __restrict__ bias, __half* __restrict__ Z)
{
    extern __shared__ __half sm[];
    __half* As = sm;                       // [2][BM][ASH]
    __half* Bs = sm + 2 * BM * ASH;        // [2][BNT][ASH]
#define AS(s,r,c) As[((s) * BM  + (r)) * ASH + (c)]
#define BS(s,r,c) Bs[((s) * BNT + (r)) * ASH + (c)]

    int tid = threadIdx.x;
    int bm = blockIdx.x * BM, bn = blockIdx.y * BNT;
    int wid = tid >> 5, lane = tid & 31;
    int g = lane >> 2, t = lane & 3;
    int wm = wid & 3, wn = wid >> 2;       // 4 x 2 warps, 32x32 per warp

    const __half* Abase = Ain + (size_t)bm * DD;
    const __half* Wbase = W + (size_t)bn * DD;

    float acc[2][4][4];
    #pragma unroll
    for (int mt = 0; mt < 2; mt++)
        #pragma unroll
        for (int nt = 0; nt < 4; nt++)
            #pragma unroll
            for (int q = 0; q < 4; q++) acc[mt][nt][q] = 0.f;

    // tile fill: A 128x32 halves = 512 x 16B chunks (2/thread), B 64x32 = 256 (1/thread)
    {
        #pragma unroll
        for (int it = 0; it < 2; it++) {
            int f = tid + it * 256;
            int r = f >> 2, ch = (f & 3) * 8;      // 8 halves per chunk
            cpa16(&AS(0, r, ch), Abase + r * DD + ch);
        }
        {
            int r = tid >> 2, ch = (tid & 3) * 8;
            cpa16(&BS(0, r, ch), Wbase + r * DD + ch);
        }
        asm volatile("cp.async.commit_group;");
    }
    __syncthreads();

    #pragma unroll 2
    for (int kb = 0; kb < DD / BK; kb++) {
        int s = kb & 1;
        if (kb < DD / BK - 1) {
            int kn = (kb + 1) * BK;
            #pragma unroll
            for (int it = 0; it < 2; it++) {
                int f = tid + it * 256;
                int r = f >> 2, ch = (f & 3) * 8;
                cpa16(&AS(s ^ 1, r, ch), Abase + r * DD + kn + ch);
            }
            {
                int r = tid >> 2, ch = (tid & 3) * 8;
                cpa16(&BS(s ^ 1, r, ch), Wbase + r * DD + kn + ch);
            }
            asm volatile("cp.async.commit_group;");
            asm volatile("cp.async.wait_group 1;");
        } else {
            asm volatile("cp.async.wait_group 0;");
        }
        __syncthreads();

        #pragma unroll
        for (int ks = 0; ks < 2; ks++) {       // two k16 steps per BK=32
            int k16 = ks * 16;
            unsigned af[2][4], bf[4][2];
            #pragma unroll
            for (int mt = 0; mt < 2; mt++) {
                int rb = wm * 32 + mt * 16;
                af[mt][0] = *(const unsigned*)&AS(s, rb + g,     k16 + 2 * t);
                af[mt][1] = *(const unsigned*)&AS(s, rb + g + 8, k16 + 2 * t);
                af[mt][2] = *(const unsigned*)&AS(s, rb + g,     k16 + 2 * t + 8);
                af[mt][3] = *(const unsigned*)&AS(s, rb + g + 8, k16 + 2 * t + 8);
            }
            #pragma unroll
            for (int nt = 0; nt < 4; nt++) {
                int nb = wn * 32 + nt * 8;
                bf[nt][0] = *(const unsigned*)&BS(s, nb + g, k16 + 2 * t);
                bf[nt][1] = *(const unsigned*)&BS(s, nb + g, k16 + 2 * t + 8);
            }
            #pragma unroll
            for (int mt = 0; mt < 2; mt++)
                #pragma unroll
                for (int nt = 0; nt < 4; nt++) {
                    asm volatile(
                        "mma.sync.aligned.m16n8k16.row.col.f32.f16.f16.f32 "
                        "{%0,%1,%2,%3},{%4,%5,%6,%7},{%8,%9},{%0,%1,%2,%3};"
                        : "+f"(acc[mt][nt][0]), "+f"(acc[mt][nt][1]),
                          "+f"(acc[mt][nt][2]), "+f"(acc[mt][nt][3])
                        : "r"(af[mt][0]), "r"(af[mt][1]), "r"(af[mt][2]), "r"(af[mt][3]),
                          "r"(bf[nt][0]), "r"(bf[nt][1]));
                }
        }
        __syncthreads();
    }

    // epilogue: += bias, convert to fp16
    #pragma unroll
    for (int mt = 0; mt < 2; mt++)
        #pragma unroll
        for (int nt = 0; nt < 4; nt++) {
            int r0 = bm + wm * 32 + mt * 16 + g;
            int col = bn + wn * 32 + nt * 8 + 2 * t;
            float b0 = bias[col], b1 = bias[col + 1];
            __half2 p0 = __floats2half2_rn(acc[mt][nt][0] + b0, acc[mt][nt][1] + b1);
            __half2 p1 = __floats2half2_rn(acc[mt][nt][2] + b0, acc[mt][nt][3] + b1);
            *reinterpret_cast<__half2*>(Z + (size_t)r0 * DD + col)       = p0;
            *reinterpret_cast<__half2*>(Z + (size_t)(r0 + 8) * DD + col) = p1;
        }
#undef AS
#undef BS
}

// ---------------- sparse aggregation (fp16 Z) + fused BN stats ----------------
__global__ __launch_bounds__(256) void agg_k(const __half* __restrict__ Z,
                                             float* __restrict__ Out, int layer) {
    __shared__ float sv[8][DD];
    int tid = threadIdx.x;
    int w = tid >> 5;
    int row = blockIdx.x * 8 + w;
    int lane = tid & 31;

    int deg = g_deg[row];
    const int* cols = &g_colidx[row * SLOT];
    float a[8];
    #pragma unroll
    for (int j = 0; j < 8; j++) a[j] = 0.f;

    int p = 0;
    for (; p + 4 <= deg; p += 4) {
        int cc[4] = {cols[p], cols[p+1], cols[p+2], cols[p+3]};
        #pragma unroll
        for (int q = 0; q < 4; q++) {
            float dv = g_dinv[cc[q]];
            uint4 u = __ldg((const uint4*)(Z + (size_t)cc[q] * DD) + lane);
            float2 f0 = __half22float2(*reinterpret_cast<__half2*>(&u.x));
            float2 f1 = __half22float2(*reinterpret_cast<__half2*>(&u.y));
            float2 f2 = __half22float2(*reinterpret_cast<__half2*>(&u.z));
            float2 f3 = __half22float2(*reinterpret_cast<__half2*>(&u.w));
            a[0] = fmaf(dv, f0.x, a[0]); a[1] = fmaf(dv, f0.y, a[1]);
            a[2] = fmaf(dv, f1.x, a[2]); a[3] = fmaf(dv, f1.y, a[3]);
            a[4] = fmaf(dv, f2.x, a[4]); a[5] = fmaf(dv, f2.y, a[5]);
            a[6] = fmaf(dv, f3.x, a[6]); a[7] = fmaf(dv, f3.y, a[7]);
        }
    }
    for (; p < deg; p++) {
        int c = cols[p];
        float dv = g_dinv[c];
        uint4 u = __ldg((const uint4*)(Z + (size_t)c * DD) + lane);
        float2 f0 = __half22float2(*reinterpret_cast<__half2*>(&u.x));
        float2 f1 = __half22float2(*reinterpret_cast<__half2*>(&u.y));
        float2 f2 = __half22float2(*reinterpret_cast<__half2*>(&u.z));
        float2 f3 = __half22float2(*reinterpret_cast<__half2*>(&u.w));
        a[0] = fmaf(dv, f0.x, a[0]); a[1] = fmaf(dv, f0.y, a[1]);
        a[2] = fmaf(dv, f1.x, a[2]); a[3] = fmaf(dv, f1.y, a[3]);
        a[4] = fmaf(dv, f2.x, a[4]); a[5] = fmaf(dv, f2.y, a[5]);
        a[6] = fmaf(dv, f3.x, a[6]); a[7] = fmaf(dv, f3.y, a[7]);
    }
    float dr = g_dinv[row];
    #pragma unroll
    for (int j = 0; j < 8; j++) a[j] *= dr;

    float4* orow = reinterpret_cast<float4*>(Out + (size_t)row * DD);
    orow[lane * 2]     = make_float4(a[0], a[1], a[2], a[3]);
    orow[lane * 2 + 1] = make_float4(a[4], a[5], a[6], a[7]);

    #pragma unroll
    for (int j = 0; j < 8; j++) sv[w][lane * 8 + j] = a[j];
    __syncthreads();
    float s = 0.f, ss = 0.f;
    #pragma unroll
    for (int r = 0; r < 8; r++) {
        float v = sv[r][tid];
        s += v;
        ss = fmaf(v, v, ss);
    }
    atomicAdd(&g_sum[layer][tid], s);
    atomicAdd(&g_sumsq[layer][tid], ss);
}

// final BN apply (fp32 out, no relu)
__global__ __launch_bounds__(256) void apply_k(const float* __restrict__ A,
                                               float* __restrict__ out,
                                               const float* __restrict__ gamma,
                                               const float* __restrict__ beta) {
    __shared__ float ssc[DD], ssh[DD];
    int tid = threadIdx.x;
    {
        float mu = g_sum[2][tid] * (1.f / NN);
        float var = g_sumsq[2][tid] * (1.f / NN) - mu * mu;
        float rs = rsqrtf(var + BN_EPS);
        float sc = gamma[tid] * rs;
        ssc[tid] = sc;
        ssh[tid] = beta[tid] - mu * sc;
    }
    __syncthreads();
    int i = blockIdx.x * 256 + tid;
    int col = (i * 4) & (DD - 1);
    float4 v = reinterpret_cast<const float4*>(A)[i];
    float4 o;
    o.x = fmaf(v.x, ssc[col],     ssh[col]);
    o.y = fmaf(v.y, ssc[col + 1], ssh[col + 1]);
    o.z = fmaf(v.z, ssc[col + 2], ssh[col + 2]);
    o.w = fmaf(v.w, ssc[col + 3], ssh[col + 3]);
    reinterpret_cast<float4*>(out)[i] = o;
}

// ---------------- launch ----------------
extern "C" void kernel_launch(void* const* d_in, const int* in_sizes, int n_in,
                              void* d_out, int out_size) {
    const float* x   = (const float*)d_in[0];
    const void*  ei  = d_in[1];
    const float* W1  = (const float*)d_in[2];
    const float* b1  = (const float*)d_in[3];
    const float* W2  = (const float*)d_in[4];
    const float* b2  = (const float*)d_in[5];
    const float* W3  = (const float*)d_in[6];
    const float* b3  = (const float*)d_in[7];
    const float* g1  = (const float*)d_in[8];
    const float* be1 = (const float*)d_in[9];
    const float* g2  = (const float*)d_in[10];
    const float* be2 = (const float*)d_in[11];
    const float* g3  = (const float*)d_in[12];
    const float* be3 = (const float*)d_in[13];
    float* out = (float*)d_out;

    void *pZ, *pA, *pBm, *pDeg, *pSum, *pSq, *pNz, *pXh, *pWh, *pAh;
    cudaGetSymbolAddress(&pZ, g_Zh);
    cudaGetSymbolAddress(&pA, g_Abuf);
    cudaGetSymbolAddress(&pBm, g_bitmap);
    cudaGetSymbolAddress(&pDeg, g_deg);
    cudaGetSymbolAddress(&pSum, g_sum);
    cudaGetSymbolAddress(&pSq, g_sumsq);
    cudaGetSymbolAddress(&pNz, g_nz);
    cudaGetSymbolAddress(&pXh, g_Xh);
    cudaGetSymbolAddress(&pWh, g_Wh);
    cudaGetSymbolAddress(&pAh, g_Ah);
    __half* Zh = (__half*)pZ;
    float*  Ab = (float*)pA;
    __half* Xh = (__half*)pXh;
    __half* Wh = (__half*)pWh;
    __half* Ah = (__half*)pAh;

    const int GEMM_SMEM = (2 * BM * ASH + 2 * BNT * ASH) * 2;   // bytes
    cudaFuncSetAttribute(gemm_k, cudaFuncAttributeMaxDynamicSharedMemorySize, GEMM_SMEM);

    static cudaStream_t s_pre = nullptr;
    static cudaEvent_t ev_fork = nullptr, ev_join = nullptr;
    if (s_pre == nullptr) {
        cudaStreamCreateWithFlags(&s_pre, cudaStreamNonBlocking);
        cudaEventCreateWithFlags(&ev_fork, cudaEventDisableTiming);
        cudaEventCreateWithFlags(&ev_join, cudaEventDisableTiming);
    }

    cudaMemsetAsync(pSum, 0, sizeof(float) * 3 * DD);
    cudaMemsetAsync(pSq, 0, sizeof(float) * 3 * DD);

    // ---- fork: preprocessing concurrent with conversions + layer-1 GEMM
    cudaEventRecord(ev_fork, 0);
    cudaStreamWaitEvent(s_pre, ev_fork, 0);
    cudaMemsetAsync(pBm, 0, sizeof(unsigned) * NN * (NN / 32), s_pre);
    cudaMemsetAsync(pDeg, 0, sizeof(int) * NN, s_pre);
    cudaMemsetAsync(pNz, 0, sizeof(int), s_pre);
    detect_k<<<16, 256, 0, s_pre>>>((const unsigned*)ei);
    dedup_k<<<(UMAX + 255) / 256, 256, 0, s_pre>>>(ei);
    dinv_k<<<NN / 256, 256, 0, s_pre>>>();
    cudaEventRecord(ev_join, s_pre);

    // main: fp16 conversions (prereqs of gemm1)
    f2h_k<<<(NN * DD / 4 + 255) / 256, 256>>>(
        (const float4*)x, (uint2*)Xh, NN * DD / 4);
    f2h_k<<<(DD * DD / 4 + 255) / 256, 256>>>(
        (const float4*)W1, (uint2*)(Wh + 0 * DD * DD), DD * DD / 4);
    f2h_k<<<(DD * DD / 4 + 255) / 256, 256>>>(
        (const float4*)W2, (uint2*)(Wh + 1 * DD * DD), DD * DD / 4);
    f2h_k<<<(DD * DD / 4 + 255) / 256, 256>>>(
        (const float4*)W3, (uint2*)(Wh + 2 * DD * DD), DD * DD / 4);

    dim3 ggrid(NN / BM, DD / BNT);

    // layer 1 — concurrent with preprocessing fork
    gemm_k<<<ggrid, 256, GEMM_SMEM>>>(Xh, Wh + 0 * DD * DD, b1, Zh);
    cudaStreamWaitEvent(0, ev_join, 0);   // agg needs CSR + dinv

    agg_k<<<NN / 8, 256>>>(Zh, Ab, 0);
    bnrelu_k<<<NN * DD / 4 / 256, 256>>>(Ab, Ah, 0, g1, be1);
    gemm_k<<<ggrid, 256, GEMM_SMEM>>>(Ah, Wh + 1 * DD * DD, b2, Zh);
    agg_k<<<NN / 8, 256>>>(Zh, Ab, 1);
    bnrelu_k<<<NN * DD / 4 / 256, 256>>>(Ab, Ah, 1, g2, be2);
    gemm_k<<<ggrid, 256, GEMM_SMEM>>>(Ah, Wh + 2 * DD * DD, b3, Zh);
    agg_k<<<NN / 8, 256>>>(Zh, Ab, 2);

    apply_k<<<NN * DD / 4 / 256, 256>>>(Ab, out, g3, be3);
}